// round 9
// baseline (speedup 1.0000x reference)
#include <cuda_runtime.h>
#include <cuda_fp16.h>
#include <cstdint>

#define BTOT   65536
#define HDIM   128
#define KTOT   384
#define NG     512
#define MT     64
#define KC     32
#define NCHUNK 12
#define THREADS 1024

// B pre-packed fp16 fragment order: [ch][w16][ks2][gp2][lane32][16B]
__device__ __half g_Bpk[NCHUNK * 16 * 2 * 2 * 32 * 8];   // 196608 halfs
__device__ float  g_Wz[KTOT];
// row permutation (bucket-sorted by (z, z_bottom))
__device__ int g_perm[BTOT];
__device__ int g_cnt[4];
__device__ int g_off[4];

#define A_STAGE_B 4096
#define B_STAGE_B 32768
#define SMEM_BYTES (2 * A_STAGE_B + 3 * B_STAGE_B)   // 8KB + 96KB = 104KB

__device__ __forceinline__ uint32_t smem_u32(const void* p) {
    uint32_t a;
    asm("{ .reg .u64 t; cvta.to.shared.u64 t, %1; cvt.u32.u64 %0, t; }" : "=r"(a) : "l"(p));
    return a;
}
__device__ __forceinline__ void cp16(uint32_t dst, const void* src) {
    asm volatile("cp.async.ca.shared.global [%0], [%1], 16;" :: "r"(dst), "l"(src));
}
__device__ __forceinline__ void cp_commit() { asm volatile("cp.async.commit_group;"); }
__device__ __forceinline__ void cp_wait1()  { asm volatile("cp.async.wait_group 1;"); }

__device__ __forceinline__ float sigm(float x)     { return 1.f / (1.f + __expf(-x)); }
__device__ __forceinline__ float tanhfast(float x) { return 1.f - 2.f / (__expf(2.f * x) + 1.f); }

__device__ __forceinline__ void mma_f16(float* d, const uint32_t* a, const uint32_t* b) {
    asm volatile(
        "mma.sync.aligned.m16n8k16.row.col.f32.f16.f16.f32 "
        "{%0,%1,%2,%3}, {%4,%5,%6,%7}, {%8,%9}, {%0,%1,%2,%3};"
        : "+f"(d[0]), "+f"(d[1]), "+f"(d[2]), "+f"(d[3])
        : "r"(a[0]), "r"(a[1]), "r"(a[2]), "r"(a[3]), "r"(b[0]), "r"(b[1]));
}

// ---------------------------------------------------------------------------
// Sort chain: bucket rows by (z, z_bottom) so tiles are (mostly) homogeneous
// ---------------------------------------------------------------------------
__global__ void reset_kernel() {
    if (threadIdx.x < 4) { g_cnt[threadIdx.x] = 0; g_off[threadIdx.x] = 0; }
}
__global__ void hist_kernel(const float* __restrict__ z, const float* __restrict__ zb) {
    int i = blockIdx.x * blockDim.x + threadIdx.x;
    if (i >= BTOT) return;
    int b = (z[i] != 0.f ? 2 : 0) + (zb[i] != 0.f ? 1 : 0);
    atomicAdd(&g_cnt[b], 1);
}
__global__ void scan_kernel() {
    int s = 0;
    for (int b = 0; b < 4; ++b) { g_off[b] = s; s += g_cnt[b]; }
}
__global__ void scatter_kernel(const float* __restrict__ z, const float* __restrict__ zb) {
    int i = blockIdx.x * blockDim.x + threadIdx.x;
    if (i >= BTOT) return;
    int b = (z[i] != 0.f ? 2 : 0) + (zb[i] != 0.f ? 1 : 0);
    int p = atomicAdd(&g_off[b], 1);
    g_perm[p] = i;
}

// ---------------------------------------------------------------------------
// Pack: [W;R;U] -> fp16 fragment-ordered B + fp32 z-column
// ---------------------------------------------------------------------------
__global__ void pack_kernel(const float* __restrict__ W, const float* __restrict__ R,
                            const float* __restrict__ U) {
    int o = blockIdx.x * blockDim.x + threadIdx.x;
    const int NB = NCHUNK * 16384;
    if (o < NB) {
        int h    = o & 1;
        int rsel = (o >> 1) & 1;
        int gsel = (o >> 2) & 1;
        int lane = (o >> 3) & 31;
        int gp   = (o >> 8) & 1;
        int ks   = (o >> 9) & 1;
        int w    = (o >> 10) & 15;
        int ch   = o >> 14;
        int tig = lane & 3, gid = lane >> 2;
        int k = ch * KC + ks * 16 + rsel * 8 + tig * 2 + h;
        int n = (gp * 2 + gsel) * 128 + w * 8 + gid;
        const float* src = (k < 128) ? W : (k < 256) ? R : U;
        g_Bpk[o] = __float2half_rn(src[(k & 127) * 513 + n]);
    } else if (o - NB < KTOT) {
        int k = o - NB;
        const float* src = (k < 128) ? W : (k < 256) ? R : U;
        g_Wz[k] = src[(k & 127) * 513 + 512];
    }
}

// ---------------------------------------------------------------------------
// Fused HMLSTM: fp16 m16n8k16 mma.sync (fp32 accum), permuted tiles with
// per-tile chunk-range skipping (W chunks iff any zb!=0, U chunks iff any
// z!=0; pure-copy tiles skip GEMM entirely; all-z=1 tiles skip the f gate).
// ---------------------------------------------------------------------------
__global__ __launch_bounds__(THREADS, 1)
void hmlstm_kernel(const float* __restrict__ hb, const float* __restrict__ hm,
                   const float* __restrict__ ht, const float* __restrict__ cm,
                   const float* __restrict__ zv, const float* __restrict__ zbv,
                   const float* __restrict__ bias, float* __restrict__ out) {
    extern __shared__ char smem[];
    char* sAc = smem;                        // [2][4096B]
    char* sBc = smem + 2 * A_STAGE_B;        // [3][32768B]
    const uint32_t sb_base = smem_u32(smem) + 2u * A_STAGE_B;

    __shared__ int sPerm[MT];
    __shared__ int sFlags;

    const int tid  = threadIdx.x;
    const int w    = tid >> 5;
    const int lane = tid & 31;
    const int gid  = lane >> 2;
    const int tig  = lane & 3;
    const int wq   = w & 15;      // col group
    const int mh   = w >> 4;      // row half
    const int m0   = blockIdx.x * MT;

    if (tid == 0) sFlags = 0;
    __syncthreads();
    if (tid < MT) {
        int o = g_perm[m0 + tid];
        sPerm[tid] = o;
        int f = 0;
        if (__ldg(zbv + o) != 0.f) f |= 1;
        if (__ldg(zv + o)  != 0.f) f |= 2; else f |= 4;
        atomicOr(&sFlags, f);
    }
    __syncthreads();
    const int flags = sFlags;
    const bool needW = flags & 1;
    const bool needU = flags & 2;
    const bool skipF = !(flags & 4);     // all z == 1
    const bool doMMA = needW || needU;
    const int  lo = needW ? 0 : 4;
    const int  hi = needU ? 12 : 8;

    // loader indexing: thread -> (row lr 0..63, k-pair c2 0..15)
    const int lr = tid >> 4;
    const int c2 = tid & 15;
    const int lmi = lr >> 4, lg8 = lr & 7, lrh = (lr >> 3) & 1;
    const int lks = c2 >> 3, lkh = (c2 >> 2) & 1, ltg = c2 & 3;
    const int abase = ((lmi * 2 + lks) * 32 + lg8 * 4 + ltg) * 16 + (lkh * 2 + lrh) * 4;

    const int   orig_lr = sPerm[lr];
    const float sc0 = __ldg(zbv + orig_lr);   // scale for W chunks
    const float sc2 = __ldg(zv + orig_lr);    // scale for U chunks

    float acc[2][4][4];
#pragma unroll
    for (int q = 0; q < 2; q++)
#pragma unroll
        for (int g = 0; g < 4; g++)
#pragma unroll
            for (int r = 0; r < 4; r++) acc[q][g][r] = 0.f;

    float2 av;
    float  zacc = 0.f;

    auto cpB = [&](int ch, int s) {
        const __half* src = g_Bpk + (size_t)ch * 16384;
        uint32_t dst = sb_base + (uint32_t)s * B_STAGE_B;
#pragma unroll
        for (int it = 0; it < 2; ++it) {
            int i = it * THREADS + tid;
            cp16(dst + (uint32_t)i * 16u, src + i * 8);
        }
    };
    auto ldgA = [&](int ch) {
        int srcid = ch >> 2, ko = (ch & 3) * KC;
        const float* x = (srcid == 0) ? hb : (srcid == 1) ? hm : ht;
        float sc = (srcid == 0) ? sc0 : (srcid == 2) ? sc2 : 1.f;
        float2 v = __ldg((const float2*)(x + (size_t)orig_lr * HDIM + ko + c2 * 2));
        v.x *= sc; v.y *= sc;
        float2 wz = __ldg((const float2*)(g_Wz + ch * KC + c2 * 2));
        zacc = fmaf(v.x, wz.x, fmaf(v.y, wz.y, zacc));
        av = v;
    };
    auto stsA = [&](int s) {
        *(__half2*)(sAc + s * A_STAGE_B + abase) = __floats2half2_rn(av.x, av.y);
    };

    if (doMMA) {
        // prologue: B(lo), B(lo+1) in flight; A(lo) staged  (hi - lo >= 8)
        cpB(lo, 0); cp_commit();
        cpB(lo + 1, 1); cp_commit();
        ldgA(lo); stsA(0);
        cp_wait1();
        __syncthreads();

        for (int ch = lo; ch < hi; ++ch) {
            int t  = ch - lo;
            int sB = t % 3;
            int sA = t & 1;
            if (ch + 2 < hi) cpB(ch + 2, (t + 2) % 3);
            cp_commit();
            if (ch + 1 < hi) ldgA(ch + 1);

            const char* A  = sAc + sA * A_STAGE_B;
            const char* Bp = sBc + sB * B_STAGE_B;

#pragma unroll
            for (int ks = 0; ks < 2; ++ks) {
                uint4 b0 = *(const uint4*)(Bp + (((wq * 2 + ks) * 2 + 0) * 32 + lane) * 16);
                uint4 b1 = *(const uint4*)(Bp + (((wq * 2 + ks) * 2 + 1) * 32 + lane) * 16);
#pragma unroll
                for (int q = 0; q < 2; ++q) {
                    int mi = mh * 2 + q;
                    uint4 a = *(const uint4*)(A + ((mi * 2 + ks) * 32 + lane) * 16);
                    const uint32_t* au = (const uint32_t*)&a;
                    mma_f16(acc[q][0], au, (const uint32_t*)&b0 + 0);
                    mma_f16(acc[q][1], au, (const uint32_t*)&b0 + 2);
                    mma_f16(acc[q][2], au, (const uint32_t*)&b1 + 0);
                    if (!skipF)
                        mma_f16(acc[q][3], au, (const uint32_t*)&b1 + 2);
                }
            }
            if (ch + 1 < hi) stsA(sA ^ 1);
            cp_wait1();
            __syncthreads();
        }
    } else {
        // pure-copy tile: only the R chunks matter, and only for the z-dot
#pragma unroll
        for (int ch = 4; ch < 8; ++ch) ldgA(ch);
    }

    // ---- z_new: exact fp32 dot over 16 threads/row, threshold sz > 0 ----
    {
        float v = zacc;
        v += __shfl_xor_sync(0xffffffffu, v, 1);
        v += __shfl_xor_sync(0xffffffffu, v, 2);
        v += __shfl_xor_sync(0xffffffffu, v, 4);
        v += __shfl_xor_sync(0xffffffffu, v, 8);
        if (c2 == 0)
            out[(size_t)BTOT * 2 * HDIM + orig_lr] =
                (v + __ldg(bias + 512) > 0.f) ? 1.f : 0.f;
    }

    // ---- epilogue: gates -> h_new, c_new (sector-coalesced float2 I/O) ----
    const int j0 = wq * 8 + tig * 2;
    float bi[2], bg[2], bo[2], bfv[2];
#pragma unroll
    for (int q = 0; q < 2; q++) {
        bi[q]  = __ldg(bias + j0 + q);
        bg[q]  = __ldg(bias + 128 + j0 + q);
        bo[q]  = __ldg(bias + 256 + j0 + q);
        bfv[q] = __ldg(bias + 384 + j0 + q);
    }
    float* outH = out;
    float* outC = out + (size_t)BTOT * HDIM;
#pragma unroll
    for (int q = 0; q < 2; ++q) {
        int mi = mh * 2 + q;
#pragma unroll
        for (int rh = 0; rh < 2; ++rh) {
            int r  = mi * 16 + gid + rh * 8;
            int gr = sPerm[r];
            float zr_ = __ldg(zv + gr), zbr = __ldg(zbv + gr);
            bool flush = (zr_ == 1.f);
            bool copyc = (zbr == 0.f);
            bool keeph = (zr_ == 0.f) && (zbr == 0.f);
            float2 cc = __ldg((const float2*)(cm + (size_t)gr * HDIM + j0));
            float2 hh = __ldg((const float2*)(hm + (size_t)gr * HDIM + j0));
            float hn[2], cn[2];
#pragma unroll
            for (int p = 0; p < 2; ++p) {
                int reg = rh * 2 + p;
                float si = acc[q][0][reg] + bi[p];
                float sg = acc[q][1][reg] + bg[p];
                float so = acc[q][2][reg] + bo[p];
                float sf = acc[q][3][reg] + bfv[p];
                float iv = sigm(si), gv = tanhfast(sg), ov = sigm(so), fv = sigm(sf);
                float ig = iv * gv;
                float cold = p ? cc.y : cc.x;
                float cnv = flush ? ig : (copyc ? cold : fmaf(cold, fv, ig));
                float hnv = keeph ? (p ? hh.y : hh.x) : tanhfast(cnv) * ov;
                cn[p] = cnv; hn[p] = hnv;
            }
            *(float2*)(outH + (size_t)gr * HDIM + j0) = make_float2(hn[0], hn[1]);
            *(float2*)(outC + (size_t)gr * HDIM + j0) = make_float2(cn[0], cn[1]);
        }
    }
}

extern "C" void kernel_launch(void* const* d_in, const int* in_sizes, int n_in,
                              void* d_out, int out_size) {
    const float* hb = (const float*)d_in[0];
    const float* h  = (const float*)d_in[1];
    const float* ht = (const float*)d_in[2];
    const float* c  = (const float*)d_in[3];
    const float* z  = (const float*)d_in[4];
    const float* zb = (const float*)d_in[5];
    const float* W  = (const float*)d_in[6];
    const float* R  = (const float*)d_in[7];
    const float* U  = (const float*)d_in[8];
    const float* b  = (const float*)d_in[9];
    float* out = (float*)d_out;
    (void)in_sizes; (void)n_in; (void)out_size;

    reset_kernel<<<1, 32>>>();
    hist_kernel<<<BTOT / 256, 256>>>(z, zb);
    scan_kernel<<<1, 1>>>();
    scatter_kernel<<<BTOT / 256, 256>>>(z, zb);

    int total = NCHUNK * 16384 + KTOT;
    pack_kernel<<<(total + 255) / 256, 256>>>(W, R, U);

    cudaFuncSetAttribute(hmlstm_kernel,
                         cudaFuncAttributeMaxDynamicSharedMemorySize, SMEM_BYTES);
    hmlstm_kernel<<<BTOT / MT, THREADS, SMEM_BYTES>>>(hb, h, ht, c, z, zb, b, out);
}

// round 10
// speedup vs baseline: 1.1522x; 1.1522x over previous
#include <cuda_runtime.h>
#include <cuda_fp16.h>
#include <cstdint>

#define BTOT   65536
#define HDIM   128
#define KTOT   384
#define NG     512
#define MT     64
#define KC     32
#define NCHUNK 12
#define THREADS 1024

// B pre-packed fp16 fragment order: [ch][w16][ks2][gp2][lane32][16B]
__device__ __half g_Bpk[NCHUNK * 16 * 2 * 2 * 32 * 8];   // 196608 halfs
__device__ float  g_Wz[KTOT];
// row permutation (bucket-sorted by (z, z_bottom))
__device__ int g_perm[BTOT];
__device__ int g_cnt[4];
__device__ int g_off[4];

#define A_STAGE_B 4096
#define B_STAGE_B 32768
#define SMEM_BYTES (2 * A_STAGE_B + 3 * B_STAGE_B)   // 8KB + 96KB = 104KB

__device__ __forceinline__ uint32_t smem_u32(const void* p) {
    uint32_t a;
    asm("{ .reg .u64 t; cvta.to.shared.u64 t, %1; cvt.u32.u64 %0, t; }" : "=r"(a) : "l"(p));
    return a;
}
__device__ __forceinline__ void cp16(uint32_t dst, const void* src) {
    asm volatile("cp.async.ca.shared.global [%0], [%1], 16;" :: "r"(dst), "l"(src));
}
__device__ __forceinline__ void cp_commit() { asm volatile("cp.async.commit_group;"); }
__device__ __forceinline__ void cp_wait1()  { asm volatile("cp.async.wait_group 1;"); }

__device__ __forceinline__ float sigm(float x)     { return 1.f / (1.f + __expf(-x)); }
__device__ __forceinline__ float tanhfast(float x) { return 1.f - 2.f / (__expf(2.f * x) + 1.f); }

__device__ __forceinline__ void mma_f16(float* d, const uint32_t* a, const uint32_t* b) {
    asm volatile(
        "mma.sync.aligned.m16n8k16.row.col.f32.f16.f16.f32 "
        "{%0,%1,%2,%3}, {%4,%5,%6,%7}, {%8,%9}, {%0,%1,%2,%3};"
        : "+f"(d[0]), "+f"(d[1]), "+f"(d[2]), "+f"(d[3])
        : "r"(a[0]), "r"(a[1]), "r"(a[2]), "r"(a[3]), "r"(b[0]), "r"(b[1]));
}

// ---------------------------------------------------------------------------
// Sort chain (warp-aggregated atomics): bucket rows by (z, z_bottom)
// ---------------------------------------------------------------------------
__global__ void reset_kernel() {
    if (threadIdx.x < 4) { g_cnt[threadIdx.x] = 0; g_off[threadIdx.x] = 0; }
}
__global__ void hist_kernel(const float* __restrict__ z, const float* __restrict__ zb) {
    int i = blockIdx.x * blockDim.x + threadIdx.x;
    int b = (z[i] != 0.f ? 2 : 0) + (zb[i] != 0.f ? 1 : 0);
    int lane = threadIdx.x & 31;
#pragma unroll
    for (int bk = 0; bk < 4; ++bk) {
        unsigned m = __ballot_sync(0xffffffffu, b == bk);
        if (lane == 0 && m) atomicAdd(&g_cnt[bk], __popc(m));
    }
}
__global__ void scan_kernel() {
    int s = 0;
    for (int b = 0; b < 4; ++b) { g_off[b] = s; s += g_cnt[b]; }
}
__global__ void scatter_kernel(const float* __restrict__ z, const float* __restrict__ zb) {
    int i = blockIdx.x * blockDim.x + threadIdx.x;
    int b = (z[i] != 0.f ? 2 : 0) + (zb[i] != 0.f ? 1 : 0);
    int lane = threadIdx.x & 31;
#pragma unroll
    for (int bk = 0; bk < 4; ++bk) {
        unsigned m = __ballot_sync(0xffffffffu, b == bk);
        if (!m) continue;
        int lead = __ffs(m) - 1;
        int base = 0;
        if (lane == lead) base = atomicAdd(&g_off[bk], __popc(m));
        base = __shfl_sync(0xffffffffu, base, lead);
        if (b == bk)
            g_perm[base + __popc(m & ((1u << lane) - 1u))] = i;
    }
}

// ---------------------------------------------------------------------------
// Pack: [W;R;U] -> fp16 fragment-ordered B + fp32 z-column
// ---------------------------------------------------------------------------
__global__ void pack_kernel(const float* __restrict__ W, const float* __restrict__ R,
                            const float* __restrict__ U) {
    int o = blockIdx.x * blockDim.x + threadIdx.x;
    const int NB = NCHUNK * 16384;
    if (o < NB) {
        int h    = o & 1;
        int rsel = (o >> 1) & 1;
        int gsel = (o >> 2) & 1;
        int lane = (o >> 3) & 31;
        int gp   = (o >> 8) & 1;
        int ks   = (o >> 9) & 1;
        int w    = (o >> 10) & 15;
        int ch   = o >> 14;
        int tig = lane & 3, gid = lane >> 2;
        int k = ch * KC + ks * 16 + rsel * 8 + tig * 2 + h;
        int n = (gp * 2 + gsel) * 128 + w * 8 + gid;
        const float* src = (k < 128) ? W : (k < 256) ? R : U;
        g_Bpk[o] = __float2half_rn(src[(k & 127) * 513 + n]);
    } else if (o - NB < KTOT) {
        int k = o - NB;
        const float* src = (k < 128) ? W : (k < 256) ? R : U;
        g_Wz[k] = src[(k & 127) * 513 + 512];
    }
}

// ---------------------------------------------------------------------------
// Fused HMLSTM: fp16 m16n8k16 mma.sync (fp32 accum), permuted tiles with
// per-tile chunk-range skipping (W chunks iff any zb!=0, U chunks iff any
// z!=0; pure-copy tiles skip GEMM entirely; all-z=1 tiles skip the f gate).
// ---------------------------------------------------------------------------
__global__ __launch_bounds__(THREADS, 1)
void hmlstm_kernel(const float* __restrict__ hb, const float* __restrict__ hm,
                   const float* __restrict__ ht, const float* __restrict__ cm,
                   const float* __restrict__ zv, const float* __restrict__ zbv,
                   const float* __restrict__ bias, float* __restrict__ out) {
    extern __shared__ char smem[];
    char* sAc = smem;                        // [2][4096B]
    char* sBc = smem + 2 * A_STAGE_B;        // [3][32768B]
    const uint32_t sb_base = smem_u32(smem) + 2u * A_STAGE_B;

    __shared__ int sPerm[MT];
    __shared__ int sFlags;

    const int tid  = threadIdx.x;
    const int w    = tid >> 5;
    const int lane = tid & 31;
    const int gid  = lane >> 2;
    const int tig  = lane & 3;
    const int wq   = w & 15;      // col group
    const int mh   = w >> 4;      // row half
    const int m0   = blockIdx.x * MT;

    if (tid == 0) sFlags = 0;
    __syncthreads();
    if (tid < MT) {
        int o = g_perm[m0 + tid];
        sPerm[tid] = o;
        int f = 0;
        if (__ldg(zbv + o) != 0.f) f |= 1;
        if (__ldg(zv + o)  != 0.f) f |= 2; else f |= 4;
        atomicOr(&sFlags, f);
    }
    __syncthreads();
    const int flags = sFlags;
    const bool needW = flags & 1;
    const bool needU = flags & 2;
    const bool skipF = !(flags & 4);     // all z == 1
    const bool doMMA = needW || needU;
    const int  lo = needW ? 0 : 4;
    const int  hi = needU ? 12 : 8;

    // loader indexing: thread -> (row lr 0..63, k-pair c2 0..15)
    const int lr = tid >> 4;
    const int c2 = tid & 15;
    const int lmi = lr >> 4, lg8 = lr & 7, lrh = (lr >> 3) & 1;
    const int lks = c2 >> 3, lkh = (c2 >> 2) & 1, ltg = c2 & 3;
    const int abase = ((lmi * 2 + lks) * 32 + lg8 * 4 + ltg) * 16 + (lkh * 2 + lrh) * 4;

    const int   orig_lr = sPerm[lr];
    const float sc0 = __ldg(zbv + orig_lr);   // scale for W chunks
    const float sc2 = __ldg(zv + orig_lr);    // scale for U chunks

    float acc[2][4][4];
#pragma unroll
    for (int q = 0; q < 2; q++)
#pragma unroll
        for (int g = 0; g < 4; g++)
#pragma unroll
            for (int r = 0; r < 4; r++) acc[q][g][r] = 0.f;

    float2 av;
    float  zacc = 0.f;

    auto cpB = [&](int ch, int s) {
        const __half* src = g_Bpk + (size_t)ch * 16384;
        uint32_t dst = sb_base + (uint32_t)s * B_STAGE_B;
#pragma unroll
        for (int it = 0; it < 2; ++it) {
            int i = it * THREADS + tid;
            cp16(dst + (uint32_t)i * 16u, src + i * 8);
        }
    };
    auto ldgA = [&](int ch) {
        int srcid = ch >> 2, ko = (ch & 3) * KC;
        const float* x = (srcid == 0) ? hb : (srcid == 1) ? hm : ht;
        float sc = (srcid == 0) ? sc0 : (srcid == 2) ? sc2 : 1.f;
        float2 v = __ldg((const float2*)(x + (size_t)orig_lr * HDIM + ko + c2 * 2));
        v.x *= sc; v.y *= sc;
        float2 wz = __ldg((const float2*)(g_Wz + ch * KC + c2 * 2));
        zacc = fmaf(v.x, wz.x, fmaf(v.y, wz.y, zacc));
        av = v;
    };
    auto stsA = [&](int s) {
        *(__half2*)(sAc + s * A_STAGE_B + abase) = __floats2half2_rn(av.x, av.y);
    };

    if (doMMA) {
        // prologue: B(lo), B(lo+1) in flight; A(lo) staged  (hi - lo >= 8)
        cpB(lo, 0); cp_commit();
        cpB(lo + 1, 1); cp_commit();
        ldgA(lo); stsA(0);
        cp_wait1();
        __syncthreads();

        for (int ch = lo; ch < hi; ++ch) {
            int t  = ch - lo;
            int sB = t % 3;
            int sA = t & 1;
            if (ch + 2 < hi) cpB(ch + 2, (t + 2) % 3);
            cp_commit();
            if (ch + 1 < hi) ldgA(ch + 1);

            const char* A  = sAc + sA * A_STAGE_B;
            const char* Bp = sBc + sB * B_STAGE_B;

#pragma unroll
            for (int ks = 0; ks < 2; ++ks) {
                uint4 b0 = *(const uint4*)(Bp + (((wq * 2 + ks) * 2 + 0) * 32 + lane) * 16);
                uint4 b1 = *(const uint4*)(Bp + (((wq * 2 + ks) * 2 + 1) * 32 + lane) * 16);
#pragma unroll
                for (int q = 0; q < 2; ++q) {
                    int mi = mh * 2 + q;
                    uint4 a = *(const uint4*)(A + ((mi * 2 + ks) * 32 + lane) * 16);
                    const uint32_t* au = (const uint32_t*)&a;
                    mma_f16(acc[q][0], au, (const uint32_t*)&b0 + 0);
                    mma_f16(acc[q][1], au, (const uint32_t*)&b0 + 2);
                    mma_f16(acc[q][2], au, (const uint32_t*)&b1 + 0);
                    if (!skipF)
                        mma_f16(acc[q][3], au, (const uint32_t*)&b1 + 2);
                }
            }
            if (ch + 1 < hi) stsA(sA ^ 1);
            cp_wait1();
            __syncthreads();
        }
    } else {
        // pure-copy tile: only the R chunks matter, and only for the z-dot
#pragma unroll
        for (int ch = 4; ch < 8; ++ch) ldgA(ch);
    }

    // ---- z_new: exact fp32 dot over 16 threads/row, threshold sz > 0 ----
    {
        float v = zacc;
        v += __shfl_xor_sync(0xffffffffu, v, 1);
        v += __shfl_xor_sync(0xffffffffu, v, 2);
        v += __shfl_xor_sync(0xffffffffu, v, 4);
        v += __shfl_xor_sync(0xffffffffu, v, 8);
        if (c2 == 0)
            out[(size_t)BTOT * 2 * HDIM + orig_lr] =
                (v + __ldg(bias + 512) > 0.f) ? 1.f : 0.f;
    }

    // ---- epilogue: gates -> h_new, c_new (sector-coalesced float2 I/O) ----
    const int j0 = wq * 8 + tig * 2;
    float bi[2], bg[2], bo[2], bfv[2];
#pragma unroll
    for (int q = 0; q < 2; q++) {
        bi[q]  = __ldg(bias + j0 + q);
        bg[q]  = __ldg(bias + 128 + j0 + q);
        bo[q]  = __ldg(bias + 256 + j0 + q);
        bfv[q] = __ldg(bias + 384 + j0 + q);
    }
    float* outH = out;
    float* outC = out + (size_t)BTOT * HDIM;
#pragma unroll
    for (int q = 0; q < 2; ++q) {
        int mi = mh * 2 + q;
#pragma unroll
        for (int rh = 0; rh < 2; ++rh) {
            int r  = mi * 16 + gid + rh * 8;
            int gr = sPerm[r];
            float zr_ = __ldg(zv + gr), zbr = __ldg(zbv + gr);
            bool flush = (zr_ == 1.f);
            bool copyc = (zbr == 0.f);
            bool keeph = (zr_ == 0.f) && (zbr == 0.f);
            float2 cc = __ldg((const float2*)(cm + (size_t)gr * HDIM + j0));
            float2 hh = __ldg((const float2*)(hm + (size_t)gr * HDIM + j0));
            float hn[2], cn[2];
#pragma unroll
            for (int p = 0; p < 2; ++p) {
                int reg = rh * 2 + p;
                float si = acc[q][0][reg] + bi[p];
                float sg = acc[q][1][reg] + bg[p];
                float so = acc[q][2][reg] + bo[p];
                float sf = acc[q][3][reg] + bfv[p];
                float iv = sigm(si), gv = tanhfast(sg), ov = sigm(so), fv = sigm(sf);
                float ig = iv * gv;
                float cold = p ? cc.y : cc.x;
                float cnv = flush ? ig : (copyc ? cold : fmaf(cold, fv, ig));
                float hnv = keeph ? (p ? hh.y : hh.x) : tanhfast(cnv) * ov;
                cn[p] = cnv; hn[p] = hnv;
            }
            *(float2*)(outH + (size_t)gr * HDIM + j0) = make_float2(hn[0], hn[1]);
            *(float2*)(outC + (size_t)gr * HDIM + j0) = make_float2(cn[0], cn[1]);
        }
    }
}

extern "C" void kernel_launch(void* const* d_in, const int* in_sizes, int n_in,
                              void* d_out, int out_size) {
    const float* hb = (const float*)d_in[0];
    const float* h  = (const float*)d_in[1];
    const float* ht = (const float*)d_in[2];
    const float* c  = (const float*)d_in[3];
    const float* z  = (const float*)d_in[4];
    const float* zb = (const float*)d_in[5];
    const float* W  = (const float*)d_in[6];
    const float* R  = (const float*)d_in[7];
    const float* U  = (const float*)d_in[8];
    const float* b  = (const float*)d_in[9];
    float* out = (float*)d_out;
    (void)in_sizes; (void)n_in; (void)out_size;

    reset_kernel<<<1, 32>>>();
    hist_kernel<<<BTOT / 256, 256>>>(z, zb);
    scan_kernel<<<1, 1>>>();
    scatter_kernel<<<BTOT / 256, 256>>>(z, zb);

    int total = NCHUNK * 16384 + KTOT;
    pack_kernel<<<(total + 255) / 256, 256>>>(W, R, U);

    cudaFuncSetAttribute(hmlstm_kernel,
                         cudaFuncAttributeMaxDynamicSharedMemorySize, SMEM_BYTES);
    hmlstm_kernel<<<BTOT / MT, THREADS, SMEM_BYTES>>>(hb, h, ht, c, z, zb, b, out);
}

// round 11
// speedup vs baseline: 1.3261x; 1.1509x over previous
#include <cuda_runtime.h>
#include <cuda_fp16.h>
#include <cstdint>

#define BTOT   65536
#define HDIM   128
#define KTOT   384
#define NG     512
#define MT     64
#define KC     32
#define NCHUNK 12
#define THREADS 512

// B pre-packed fp16 fragment order: [ch][w16][ks2][gp2][lane32][16B]
__device__ __half g_Bpk[NCHUNK * 16 * 2 * 2 * 32 * 8];   // 196608 halfs
__device__ float  g_Wz[KTOT];
// row permutation (bucket-sorted by (z, z_bottom))
__device__ int g_perm[BTOT];
__device__ int g_cnt[4];
__device__ int g_off[4];

#define A_STAGE_B 4096
#define B_STAGE_B 16384
#define SMEM_BYTES (2 * A_STAGE_B + 3 * B_STAGE_B)   // 8KB + 48KB = 56KB

__device__ __forceinline__ uint32_t smem_u32(const void* p) {
    uint32_t a;
    asm("{ .reg .u64 t; cvta.to.shared.u64 t, %1; cvt.u32.u64 %0, t; }" : "=r"(a) : "l"(p));
    return a;
}
__device__ __forceinline__ void cp16(uint32_t dst, const void* src) {
    asm volatile("cp.async.ca.shared.global [%0], [%1], 16;" :: "r"(dst), "l"(src));
}
__device__ __forceinline__ void cp_commit() { asm volatile("cp.async.commit_group;"); }
__device__ __forceinline__ void cp_wait1()  { asm volatile("cp.async.wait_group 1;"); }

__device__ __forceinline__ float sigm(float x)     { return 1.f / (1.f + __expf(-x)); }
__device__ __forceinline__ float tanhfast(float x) { return 1.f - 2.f / (__expf(2.f * x) + 1.f); }

__device__ __forceinline__ void mma_f16(float* d, const uint32_t* a, const uint32_t* b) {
    asm volatile(
        "mma.sync.aligned.m16n8k16.row.col.f32.f16.f16.f32 "
        "{%0,%1,%2,%3}, {%4,%5,%6,%7}, {%8,%9}, {%0,%1,%2,%3};"
        : "+f"(d[0]), "+f"(d[1]), "+f"(d[2]), "+f"(d[3])
        : "r"(a[0]), "r"(a[1]), "r"(a[2]), "r"(a[3]), "r"(b[0]), "r"(b[1]));
}

// ---------------------------------------------------------------------------
// Sort chain (block-aggregated): bucket rows by (z, z_bottom)
// ---------------------------------------------------------------------------
__global__ void reset_kernel() {
    if (threadIdx.x < 4) { g_cnt[threadIdx.x] = 0; g_off[threadIdx.x] = 0; }
}
__global__ void hist_kernel(const float* __restrict__ z, const float* __restrict__ zb) {
    __shared__ int cnt[4];
    int tid = threadIdx.x;
    if (tid < 4) cnt[tid] = 0;
    __syncthreads();
    int i = blockIdx.x * 256 + tid;
    int b = (z[i] != 0.f ? 2 : 0) + (zb[i] != 0.f ? 1 : 0);
    int lane = tid & 31;
#pragma unroll
    for (int bk = 0; bk < 4; ++bk) {
        unsigned m = __ballot_sync(0xffffffffu, b == bk);
        if (lane == 0 && m) atomicAdd(&cnt[bk], __popc(m));
    }
    __syncthreads();
    if (tid < 4 && cnt[tid]) atomicAdd(&g_cnt[tid], cnt[tid]);
}
__global__ void scan_kernel() {
    int s = 0;
    for (int b = 0; b < 4; ++b) { g_off[b] = s; s += g_cnt[b]; }
}
__global__ void scatter_kernel(const float* __restrict__ z, const float* __restrict__ zb) {
    __shared__ int wcnt[8][4];
    __shared__ int wpref[8][4];
    __shared__ int bbase[4];
    int tid = threadIdx.x, w = tid >> 5, lane = tid & 31;
    int i = blockIdx.x * 256 + tid;
    int b = (z[i] != 0.f ? 2 : 0) + (zb[i] != 0.f ? 1 : 0);
    unsigned mb = 0;
#pragma unroll
    for (int bk = 0; bk < 4; ++bk) {
        unsigned m = __ballot_sync(0xffffffffu, b == bk);
        if (b == bk) mb = m;
        if (lane == 0) wcnt[w][bk] = __popc(m);
    }
    __syncthreads();
    if (tid < 4) {
        int s = 0;
#pragma unroll
        for (int ww = 0; ww < 8; ++ww) { wpref[ww][tid] = s; s += wcnt[ww][tid]; }
        bbase[tid] = s ? atomicAdd(&g_off[tid], s) : 0;
    }
    __syncthreads();
    g_perm[bbase[b] + wpref[w][b] + __popc(mb & ((1u << lane) - 1u))] = i;
}

// ---------------------------------------------------------------------------
// Pack: [W;R;U] -> fp16 fragment-ordered B + fp32 z-column
// ---------------------------------------------------------------------------
__global__ void pack_kernel(const float* __restrict__ W, const float* __restrict__ R,
                            const float* __restrict__ U) {
    int o = blockIdx.x * blockDim.x + threadIdx.x;
    const int NB = NCHUNK * 16384;
    if (o < NB) {
        int h    = o & 1;
        int rsel = (o >> 1) & 1;
        int gsel = (o >> 2) & 1;
        int lane = (o >> 3) & 31;
        int gp   = (o >> 8) & 1;
        int ks   = (o >> 9) & 1;
        int w    = (o >> 10) & 15;
        int ch   = o >> 14;
        int tig = lane & 3, gid = lane >> 2;
        int k = ch * KC + ks * 16 + rsel * 8 + tig * 2 + h;
        int n = (gp * 2 + gsel) * 128 + w * 8 + gid;
        const float* src = (k < 128) ? W : (k < 256) ? R : U;
        g_Bpk[o] = __float2half_rn(src[(k & 127) * 513 + n]);
    } else if (o - NB < KTOT) {
        int k = o - NB;
        const float* src = (k < 128) ? W : (k < 256) ? R : U;
        g_Wz[k] = src[(k & 127) * 513 + 512];
    }
}

// ---------------------------------------------------------------------------
// Fused HMLSTM: fp16 m16n8k16 mma.sync (fp32 accum), N-split CTAs (2/SM).
// blockIdx: tile = bx>>1 (64 permuted rows), nh = bx&1 (gate-col half).
// Warp w (0..15): wq = w&7 -> cols (nh*8+wq)*8, mq = w>>3 -> rows mq*32..+31.
// ---------------------------------------------------------------------------
__global__ __launch_bounds__(THREADS, 2)
void hmlstm_kernel(const float* __restrict__ hb, const float* __restrict__ hm,
                   const float* __restrict__ ht, const float* __restrict__ cm,
                   const float* __restrict__ zv, const float* __restrict__ zbv,
                   const float* __restrict__ bias, float* __restrict__ out) {
    extern __shared__ char smem[];
    char* sAc = smem;                        // [2][4096B]
    char* sBc = smem + 2 * A_STAGE_B;        // [3][16384B]
    const uint32_t sb_base = smem_u32(smem) + 2u * A_STAGE_B;

    __shared__ int sPerm[MT];
    __shared__ int sFlags;

    const int tid  = threadIdx.x;
    const int w    = tid >> 5;
    const int lane = tid & 31;
    const int gid  = lane >> 2;
    const int tig  = lane & 3;
    const int wq   = w & 7;       // col group within half
    const int mq   = w >> 3;      // row half of tile
    const int tile = blockIdx.x >> 1;
    const int nh   = blockIdx.x & 1;
    const int m0   = tile * MT;

    if (tid == 0) sFlags = 0;
    __syncthreads();
    if (tid < MT) {
        int o = g_perm[m0 + tid];
        sPerm[tid] = o;
        int f = 0;
        if (__ldg(zbv + o) != 0.f) f |= 1;
        if (__ldg(zv + o)  != 0.f) f |= 2; else f |= 4;
        atomicOr(&sFlags, f);
    }
    __syncthreads();
    const int flags = sFlags;
    const bool needW = flags & 1;
    const bool needU = flags & 2;
    const bool skipF = !(flags & 4);     // all z == 1
    const bool doMMA = needW || needU;
    const int  lo = needW ? 0 : 4;
    const int  hi = needU ? 12 : 8;

    // loader indexing: thread -> (row lr 0..63, float4 k-slice lf 0..7)
    const int lr = tid >> 3;
    const int lf = tid & 7;
    const int lmi = lr >> 4, lg8 = lr & 7, lrh = (lr >> 3) & 1;
    const int lks = lf >> 2, lkh = (lf >> 1) & 1, ltg = (lf & 1) * 2;
    const int abase = ((lmi * 2 + lks) * 32 + lg8 * 4 + ltg) * 16 + (lkh * 2 + lrh) * 4;

    const int   orig_lr = sPerm[lr];
    const float sc0 = __ldg(zbv + orig_lr);   // scale for W chunks
    const float sc2 = __ldg(zv + orig_lr);    // scale for U chunks

    float acc[2][4][4];
#pragma unroll
    for (int q = 0; q < 2; q++)
#pragma unroll
        for (int g = 0; g < 4; g++)
#pragma unroll
            for (int r = 0; r < 4; r++) acc[q][g][r] = 0.f;

    float4 av;
    float  zacc = 0.f;

    auto cpB = [&](int ch, int s) {
        const __half* src = g_Bpk + (size_t)ch * 16384 + nh * 8192;
        uint32_t dst = sb_base + (uint32_t)s * B_STAGE_B;
#pragma unroll
        for (int it = 0; it < 2; ++it) {
            int i = it * THREADS + tid;          // 0..1023 16B units
            cp16(dst + (uint32_t)i * 16u, src + i * 8);
        }
    };
    auto ldgA = [&](int ch) {
        int srcid = ch >> 2, ko = (ch & 3) * KC;
        const float* x = (srcid == 0) ? hb : (srcid == 1) ? hm : ht;
        float sc = (srcid == 0) ? sc0 : (srcid == 2) ? sc2 : 1.f;
        float4 v = __ldg((const float4*)(x + (size_t)orig_lr * HDIM + ko + lf * 4));
        v.x *= sc; v.y *= sc; v.z *= sc; v.w *= sc;
        float4 wz = __ldg((const float4*)(g_Wz + ch * KC + lf * 4));
        zacc = fmaf(v.x, wz.x, fmaf(v.y, wz.y, fmaf(v.z, wz.z, fmaf(v.w, wz.w, zacc))));
        av = v;
    };
    auto stsA = [&](int s) {
        char* A = sAc + s * A_STAGE_B;
        *(__half2*)(A + abase)      = __floats2half2_rn(av.x, av.y);
        *(__half2*)(A + abase + 16) = __floats2half2_rn(av.z, av.w);
    };

    if (doMMA) {
        // prologue: B(lo), B(lo+1) in flight; A(lo) staged  (hi - lo >= 8)
        cpB(lo, 0); cp_commit();
        cpB(lo + 1, 1); cp_commit();
        ldgA(lo); stsA(0);
        cp_wait1();
        __syncthreads();

        for (int ch = lo; ch < hi; ++ch) {
            int t  = ch - lo;
            int sB = t % 3;
            int sA = t & 1;
            if (ch + 2 < hi) cpB(ch + 2, (t + 2) % 3);
            cp_commit();
            if (ch + 1 < hi) ldgA(ch + 1);

            const char* A  = sAc + sA * A_STAGE_B;
            const char* Bp = sBc + sB * B_STAGE_B;

#pragma unroll
            for (int ks = 0; ks < 2; ++ks) {
                uint4 b0 = *(const uint4*)(Bp + (((wq * 2 + ks) * 2 + 0) * 32 + lane) * 16);
                uint4 b1 = *(const uint4*)(Bp + (((wq * 2 + ks) * 2 + 1) * 32 + lane) * 16);
#pragma unroll
                for (int q = 0; q < 2; ++q) {
                    int mi = mq * 2 + q;
                    uint4 a = *(const uint4*)(A + ((mi * 2 + ks) * 32 + lane) * 16);
                    const uint32_t* au = (const uint32_t*)&a;
                    mma_f16(acc[q][0], au, (const uint32_t*)&b0 + 0);
                    mma_f16(acc[q][1], au, (const uint32_t*)&b0 + 2);
                    mma_f16(acc[q][2], au, (const uint32_t*)&b1 + 0);
                    if (!skipF)
                        mma_f16(acc[q][3], au, (const uint32_t*)&b1 + 2);
                }
            }
            if (ch + 1 < hi) stsA(sA ^ 1);
            cp_wait1();
            __syncthreads();
        }
    } else if (nh == 0) {
        // pure-copy tile: only the R chunks matter, and only for the z-dot
#pragma unroll
        for (int ch = 4; ch < 8; ++ch) ldgA(ch);
    }

    // ---- z_new (nh==0 CTA only): exact fp32 dot, threshold sz > 0 ----
    if (nh == 0) {
        float v = zacc;
        v += __shfl_xor_sync(0xffffffffu, v, 1);
        v += __shfl_xor_sync(0xffffffffu, v, 2);
        v += __shfl_xor_sync(0xffffffffu, v, 4);
        if (lf == 0)
            out[(size_t)BTOT * 2 * HDIM + orig_lr] =
                (v + __ldg(bias + 512) > 0.f) ? 1.f : 0.f;
    }

    // ---- epilogue: gates -> h_new, c_new (sector-coalesced float2 I/O) ----
    const int j0 = (nh * 8 + wq) * 8 + tig * 2;
    float bi[2], bg[2], bo[2], bfv[2];
#pragma unroll
    for (int q = 0; q < 2; q++) {
        bi[q]  = __ldg(bias + j0 + q);
        bg[q]  = __ldg(bias + 128 + j0 + q);
        bo[q]  = __ldg(bias + 256 + j0 + q);
        bfv[q] = __ldg(bias + 384 + j0 + q);
    }
    float* outH = out;
    float* outC = out + (size_t)BTOT * HDIM;
#pragma unroll
    for (int q = 0; q < 2; ++q) {
        int mi = mq * 2 + q;
#pragma unroll
        for (int rh = 0; rh < 2; ++rh) {
            int r  = mi * 16 + gid + rh * 8;
            int gr = sPerm[r];
            float zr_ = __ldg(zv + gr), zbr = __ldg(zbv + gr);
            bool flush = (zr_ == 1.f);
            bool copyc = (zbr == 0.f);
            bool keeph = (zr_ == 0.f) && (zbr == 0.f);
            float2 cc = __ldg((const float2*)(cm + (size_t)gr * HDIM + j0));
            float2 hh = __ldg((const float2*)(hm + (size_t)gr * HDIM + j0));
            float hn[2], cn[2];
#pragma unroll
            for (int p = 0; p < 2; ++p) {
                int reg = rh * 2 + p;
                float si = acc[q][0][reg] + bi[p];
                float sg = acc[q][1][reg] + bg[p];
                float so = acc[q][2][reg] + bo[p];
                float sf = acc[q][3][reg] + bfv[p];
                float iv = sigm(si), gv = tanhfast(sg), ov = sigm(so), fv = sigm(sf);
                float ig = iv * gv;
                float cold = p ? cc.y : cc.x;
                float cnv = flush ? ig : (copyc ? cold : fmaf(cold, fv, ig));
                float hnv = keeph ? (p ? hh.y : hh.x) : tanhfast(cnv) * ov;
                cn[p] = cnv; hn[p] = hnv;
            }
            *(float2*)(outH + (size_t)gr * HDIM + j0) = make_float2(hn[0], hn[1]);
            *(float2*)(outC + (size_t)gr * HDIM + j0) = make_float2(cn[0], cn[1]);
        }
    }
}

extern "C" void kernel_launch(void* const* d_in, const int* in_sizes, int n_in,
                              void* d_out, int out_size) {
    const float* hb = (const float*)d_in[0];
    const float* h  = (const float*)d_in[1];
    const float* ht = (const float*)d_in[2];
    const float* c  = (const float*)d_in[3];
    const float* z  = (const float*)d_in[4];
    const float* zb = (const float*)d_in[5];
    const float* W  = (const float*)d_in[6];
    const float* R  = (const float*)d_in[7];
    const float* U  = (const float*)d_in[8];
    const float* b  = (const float*)d_in[9];
    float* out = (float*)d_out;
    (void)in_sizes; (void)n_in; (void)out_size;

    reset_kernel<<<1, 32>>>();
    hist_kernel<<<BTOT / 256, 256>>>(z, zb);
    scan_kernel<<<1, 1>>>();
    scatter_kernel<<<BTOT / 256, 256>>>(z, zb);

    int total = NCHUNK * 16384 + KTOT;
    pack_kernel<<<(total + 255) / 256, 256>>>(W, R, U);

    cudaFuncSetAttribute(hmlstm_kernel,
                         cudaFuncAttributeMaxDynamicSharedMemorySize, SMEM_BYTES);
    hmlstm_kernel<<<2 * (BTOT / MT), THREADS, SMEM_BYTES>>>(hb, h, ht, c, z, zb, b, out);
}

// round 12
// speedup vs baseline: 1.5168x; 1.1438x over previous
#include <cuda_runtime.h>
#include <cuda_fp16.h>
#include <cstdint>

#define BTOT   65536
#define HDIM   128
#define KTOT   384
#define NG     512
#define MT     64
#define KC     32
#define NCHUNK 12
#define THREADS 512

// B pre-packed fp16 fragment order: [ch][w16][ks2][gp2][lane32][16B]
__device__ __half g_Bpk[NCHUNK * 16 * 2 * 2 * 32 * 8];   // 196608 halfs
__device__ float  g_Wz[KTOT];
// row permutation (bucket-sorted by (z, z_bottom))
__device__ int g_perm[BTOT];
__device__ int g_cnt[4];
__device__ int g_off[4];

#define A_STAGE_B 4096
#define B_STAGE_B 16384
#define SMEM_BYTES (NCHUNK * A_STAGE_B + 3 * B_STAGE_B)   // 48KB + 48KB = 96KB

__device__ __forceinline__ uint32_t smem_u32(const void* p) {
    uint32_t a;
    asm("{ .reg .u64 t; cvta.to.shared.u64 t, %1; cvt.u32.u64 %0, t; }" : "=r"(a) : "l"(p));
    return a;
}
__device__ __forceinline__ void cp16(uint32_t dst, const void* src) {
    asm volatile("cp.async.ca.shared.global [%0], [%1], 16;" :: "r"(dst), "l"(src));
}
__device__ __forceinline__ void cp_commit() { asm volatile("cp.async.commit_group;"); }
__device__ __forceinline__ void cp_wait1()  { asm volatile("cp.async.wait_group 1;"); }

__device__ __forceinline__ float sigm(float x)     { return 1.f / (1.f + __expf(-x)); }
__device__ __forceinline__ float tanhfast(float x) { return 1.f - 2.f / (__expf(2.f * x) + 1.f); }

__device__ __forceinline__ void mma_f16(float* d, const uint32_t* a, const uint32_t* b) {
    asm volatile(
        "mma.sync.aligned.m16n8k16.row.col.f32.f16.f16.f32 "
        "{%0,%1,%2,%3}, {%4,%5,%6,%7}, {%8,%9}, {%0,%1,%2,%3};"
        : "+f"(d[0]), "+f"(d[1]), "+f"(d[2]), "+f"(d[3])
        : "r"(a[0]), "r"(a[1]), "r"(a[2]), "r"(a[3]), "r"(b[0]), "r"(b[1]));
}

// ---------------------------------------------------------------------------
// Sort chain (block-aggregated): bucket rows by (z, z_bottom)
// ---------------------------------------------------------------------------
__global__ void reset_kernel() {
    if (threadIdx.x < 4) { g_cnt[threadIdx.x] = 0; g_off[threadIdx.x] = 0; }
}
__global__ void hist_kernel(const float* __restrict__ z, const float* __restrict__ zb) {
    __shared__ int cnt[4];
    int tid = threadIdx.x;
    if (tid < 4) cnt[tid] = 0;
    __syncthreads();
    int i = blockIdx.x * 256 + tid;
    int b = (z[i] != 0.f ? 2 : 0) + (zb[i] != 0.f ? 1 : 0);
    int lane = tid & 31;
#pragma unroll
    for (int bk = 0; bk < 4; ++bk) {
        unsigned m = __ballot_sync(0xffffffffu, b == bk);
        if (lane == 0 && m) atomicAdd(&cnt[bk], __popc(m));
    }
    __syncthreads();
    if (tid < 4 && cnt[tid]) atomicAdd(&g_cnt[tid], cnt[tid]);
}
__global__ void scan_kernel() {
    int s = 0;
    for (int b = 0; b < 4; ++b) { g_off[b] = s; s += g_cnt[b]; }
}
__global__ void scatter_kernel(const float* __restrict__ z, const float* __restrict__ zb) {
    __shared__ int wcnt[8][4];
    __shared__ int wpref[8][4];
    __shared__ int bbase[4];
    int tid = threadIdx.x, w = tid >> 5, lane = tid & 31;
    int i = blockIdx.x * 256 + tid;
    int b = (z[i] != 0.f ? 2 : 0) + (zb[i] != 0.f ? 1 : 0);
    unsigned mb = 0;
#pragma unroll
    for (int bk = 0; bk < 4; ++bk) {
        unsigned m = __ballot_sync(0xffffffffu, b == bk);
        if (b == bk) mb = m;
        if (lane == 0) wcnt[w][bk] = __popc(m);
    }
    __syncthreads();
    if (tid < 4) {
        int s = 0;
#pragma unroll
        for (int ww = 0; ww < 8; ++ww) { wpref[ww][tid] = s; s += wcnt[ww][tid]; }
        bbase[tid] = s ? atomicAdd(&g_off[tid], s) : 0;
    }
    __syncthreads();
    g_perm[bbase[b] + wpref[w][b] + __popc(mb & ((1u << lane) - 1u))] = i;
}

// ---------------------------------------------------------------------------
// Pack: [W;R;U] -> fp16 fragment-ordered B + fp32 z-column
// ---------------------------------------------------------------------------
__global__ void pack_kernel(const float* __restrict__ W, const float* __restrict__ R,
                            const float* __restrict__ U) {
    int o = blockIdx.x * blockDim.x + threadIdx.x;
    const int NB = NCHUNK * 16384;
    if (o < NB) {
        int h    = o & 1;
        int rsel = (o >> 1) & 1;
        int gsel = (o >> 2) & 1;
        int lane = (o >> 3) & 31;
        int gp   = (o >> 8) & 1;
        int ks   = (o >> 9) & 1;
        int w    = (o >> 10) & 15;
        int ch   = o >> 14;
        int tig = lane & 3, gid = lane >> 2;
        int k = ch * KC + ks * 16 + rsel * 8 + tig * 2 + h;
        int n = (gp * 2 + gsel) * 128 + w * 8 + gid;
        const float* src = (k < 128) ? W : (k < 256) ? R : U;
        g_Bpk[o] = __float2half_rn(src[(k & 127) * 513 + n]);
    } else if (o - NB < KTOT) {
        int k = o - NB;
        const float* src = (k < 128) ? W : (k < 256) ? R : U;
        g_Wz[k] = src[(k & 127) * 513 + 512];
    }
}

// ---------------------------------------------------------------------------
// Fused HMLSTM: fp16 m16n8k16 mma.sync (fp32 accum), N-split CTAs (2/SM).
// All A chunks loaded/converted in the prologue (high MLP, one barrier) so
// the MMA loop has no global-latency dependencies; B stays 3-stage cp.async.
// ---------------------------------------------------------------------------
__global__ __launch_bounds__(THREADS, 2)
void hmlstm_kernel(const float* __restrict__ hb, const float* __restrict__ hm,
                   const float* __restrict__ ht, const float* __restrict__ cm,
                   const float* __restrict__ zv, const float* __restrict__ zbv,
                   const float* __restrict__ bias, float* __restrict__ out) {
    extern __shared__ char smem[];
    char* sAc = smem;                                  // [NCHUNK][4096B]
    char* sBc = smem + NCHUNK * A_STAGE_B;             // [3][16384B]
    const uint32_t sb_base = smem_u32(smem) + (uint32_t)(NCHUNK * A_STAGE_B);

    __shared__ int sPerm[MT];
    __shared__ int sFlags;

    const int tid  = threadIdx.x;
    const int w    = tid >> 5;
    const int lane = tid & 31;
    const int gid  = lane >> 2;
    const int tig  = lane & 3;
    const int wq   = w & 7;       // col group within half
    const int mq   = w >> 3;      // row half of tile
    const int tile = blockIdx.x >> 1;
    const int nh   = blockIdx.x & 1;
    const int m0   = tile * MT;

    if (tid == 0) sFlags = 0;
    __syncthreads();
    if (tid < MT) {
        int o = g_perm[m0 + tid];
        sPerm[tid] = o;
        int f = 0;
        if (__ldg(zbv + o) != 0.f) f |= 1;
        if (__ldg(zv + o)  != 0.f) f |= 2; else f |= 4;
        atomicOr(&sFlags, f);
    }
    __syncthreads();
    const int flags = sFlags;
    const bool needW = flags & 1;
    const bool needU = flags & 2;
    const bool skipF = !(flags & 4);     // all z == 1
    const bool doMMA = needW || needU;
    const int  lo = needW ? 0 : 4;
    const int  hi = needU ? 12 : 8;

    // loader indexing: thread -> (row lr 0..63, float4 k-slice lf 0..7)
    const int lr = tid >> 3;
    const int lf = tid & 7;
    const int lmi = lr >> 4, lg8 = lr & 7, lrh = (lr >> 3) & 1;
    const int lks = lf >> 2, lkh = (lf >> 1) & 1, ltg = (lf & 1) * 2;
    const int abase = ((lmi * 2 + lks) * 32 + lg8 * 4 + ltg) * 16 + (lkh * 2 + lrh) * 4;

    const int   orig_lr = sPerm[lr];
    const float sc0 = __ldg(zbv + orig_lr);   // scale for W chunks
    const float sc2 = __ldg(zv + orig_lr);    // scale for U chunks

    float acc[2][4][4];
#pragma unroll
    for (int q = 0; q < 2; q++)
#pragma unroll
        for (int g = 0; g < 4; g++)
#pragma unroll
            for (int r = 0; r < 4; r++) acc[q][g][r] = 0.f;

    float zacc = 0.f;

    auto cpB = [&](int ch, int s) {
        const __half* src = g_Bpk + (size_t)ch * 16384 + nh * 8192;
        uint32_t dst = sb_base + (uint32_t)s * B_STAGE_B;
#pragma unroll
        for (int it = 0; it < 2; ++it) {
            int i = it * THREADS + tid;          // 0..1023 16B units
            cp16(dst + (uint32_t)i * 16u, src + i * 8);
        }
    };

    if (doMMA) {
        // B pipeline prologue
        cpB(lo, 0); cp_commit();
        cpB(lo + 1, 1); cp_commit();

        // Load ALL A chunks [lo,hi): grouped LDGs (MLP=4), fold in z-dot,
        // convert to fp16 fragments in smem. Chunks cg..cg+3 share srcid.
        for (int cg = lo; cg < hi; cg += 4) {
            int srcid = cg >> 2;
            const float* x = (srcid == 0) ? hb : (srcid == 1) ? hm : ht;
            float sc = (srcid == 0) ? sc0 : (srcid == 2) ? sc2 : 1.f;
            float4 v[4];
#pragma unroll
            for (int j = 0; j < 4; ++j)
                v[j] = __ldg((const float4*)(x + (size_t)orig_lr * HDIM + j * KC + lf * 4));
#pragma unroll
            for (int j = 0; j < 4; ++j) {
                float4 t = v[j];
                t.x *= sc; t.y *= sc; t.z *= sc; t.w *= sc;
                float4 wz = __ldg((const float4*)(g_Wz + (cg + j) * KC + lf * 4));
                zacc = fmaf(t.x, wz.x, fmaf(t.y, wz.y, fmaf(t.z, wz.z, fmaf(t.w, wz.w, zacc))));
                char* A = sAc + (cg - lo + j) * A_STAGE_B;
                *(__half2*)(A + abase)      = __floats2half2_rn(t.x, t.y);
                *(__half2*)(A + abase + 16) = __floats2half2_rn(t.z, t.w);
            }
        }

        cp_wait1();
        __syncthreads();

        for (int ch = lo; ch < hi; ++ch) {
            int t  = ch - lo;
            int sB = t % 3;
            if (ch + 2 < hi) cpB(ch + 2, (t + 2) % 3);
            cp_commit();

            const char* A  = sAc + t * A_STAGE_B;
            const char* Bp = sBc + sB * B_STAGE_B;

#pragma unroll
            for (int ks = 0; ks < 2; ++ks) {
                uint4 b0 = *(const uint4*)(Bp + (((wq * 2 + ks) * 2 + 0) * 32 + lane) * 16);
                uint4 b1 = *(const uint4*)(Bp + (((wq * 2 + ks) * 2 + 1) * 32 + lane) * 16);
#pragma unroll
                for (int q = 0; q < 2; ++q) {
                    int mi = mq * 2 + q;
                    uint4 a = *(const uint4*)(A + ((mi * 2 + ks) * 32 + lane) * 16);
                    const uint32_t* au = (const uint32_t*)&a;
                    mma_f16(acc[q][0], au, (const uint32_t*)&b0 + 0);
                    mma_f16(acc[q][1], au, (const uint32_t*)&b0 + 2);
                    mma_f16(acc[q][2], au, (const uint32_t*)&b1 + 0);
                    if (!skipF)
                        mma_f16(acc[q][3], au, (const uint32_t*)&b1 + 2);
                }
            }
            cp_wait1();
            __syncthreads();
        }
    } else if (nh == 0) {
        // pure-copy tile: only the R chunks matter, and only for the z-dot
        const float* x = hm;
        float4 v[4];
#pragma unroll
        for (int j = 0; j < 4; ++j)
            v[j] = __ldg((const float4*)(x + (size_t)orig_lr * HDIM + j * KC + lf * 4));
#pragma unroll
        for (int j = 0; j < 4; ++j) {
            float4 wz = __ldg((const float4*)(g_Wz + (4 + j) * KC + lf * 4));
            zacc = fmaf(v[j].x, wz.x, fmaf(v[j].y, wz.y,
                   fmaf(v[j].z, wz.z, fmaf(v[j].w, wz.w, zacc))));
        }
    }

    // ---- z_new (nh==0 CTA only): exact fp32 dot, threshold sz > 0 ----
    if (nh == 0) {
        float v = zacc;
        v += __shfl_xor_sync(0xffffffffu, v, 1);
        v += __shfl_xor_sync(0xffffffffu, v, 2);
        v += __shfl_xor_sync(0xffffffffu, v, 4);
        if (lf == 0)
            out[(size_t)BTOT * 2 * HDIM + orig_lr] =
                (v + __ldg(bias + 512) > 0.f) ? 1.f : 0.f;
    }

    // ---- epilogue: gates -> h_new, c_new (sector-coalesced float2 I/O) ----
    const int j0 = (nh * 8 + wq) * 8 + tig * 2;
    float bi[2], bg[2], bo[2], bfv[2];
#pragma unroll
    for (int q = 0; q < 2; q++) {
        bi[q]  = __ldg(bias + j0 + q);
        bg[q]  = __ldg(bias + 128 + j0 + q);
        bo[q]  = __ldg(bias + 256 + j0 + q);
        bfv[q] = __ldg(bias + 384 + j0 + q);
    }
    float* outH = out;
    float* outC = out + (size_t)BTOT * HDIM;
#pragma unroll
    for (int q = 0; q < 2; ++q) {
        int mi = mq * 2 + q;
#pragma unroll
        for (int rh = 0; rh < 2; ++rh) {
            int r  = mi * 16 + gid + rh * 8;
            int gr = sPerm[r];
            float zr_ = __ldg(zv + gr), zbr = __ldg(zbv + gr);
            bool flush = (zr_ == 1.f);
            bool copyc = (zbr == 0.f);
            bool keeph = (zr_ == 0.f) && (zbr == 0.f);
            float2 cc = __ldg((const float2*)(cm + (size_t)gr * HDIM + j0));
            float2 hh = __ldg((const float2*)(hm + (size_t)gr * HDIM + j0));
            float hn[2], cn[2];
#pragma unroll
            for (int p = 0; p < 2; ++p) {
                int reg = rh * 2 + p;
                float si = acc[q][0][reg] + bi[p];
                float sg = acc[q][1][reg] + bg[p];
                float so = acc[q][2][reg] + bo[p];
                float sf = acc[q][3][reg] + bfv[p];
                float iv = sigm(si), gv = tanhfast(sg), ov = sigm(so), fv = sigm(sf);
                float ig = iv * gv;
                float cold = p ? cc.y : cc.x;
                float cnv = flush ? ig : (copyc ? cold : fmaf(cold, fv, ig));
                float hnv = keeph ? (p ? hh.y : hh.x) : tanhfast(cnv) * ov;
                cn[p] = cnv; hn[p] = hnv;
            }
            *(float2*)(outH + (size_t)gr * HDIM + j0) = make_float2(hn[0], hn[1]);
            *(float2*)(outC + (size_t)gr * HDIM + j0) = make_float2(cn[0], cn[1]);
        }
    }
}

extern "C" void kernel_launch(void* const* d_in, const int* in_sizes, int n_in,
                              void* d_out, int out_size) {
    const float* hb = (const float*)d_in[0];
    const float* h  = (const float*)d_in[1];
    const float* ht = (const float*)d_in[2];
    const float* c  = (const float*)d_in[3];
    const float* z  = (const float*)d_in[4];
    const float* zb = (const float*)d_in[5];
    const float* W  = (const float*)d_in[6];
    const float* R  = (const float*)d_in[7];
    const float* U  = (const float*)d_in[8];
    const float* b  = (const float*)d_in[9];
    float* out = (float*)d_out;
    (void)in_sizes; (void)n_in; (void)out_size;

    reset_kernel<<<1, 32>>>();
    hist_kernel<<<BTOT / 256, 256>>>(z, zb);
    scan_kernel<<<1, 1>>>();
    scatter_kernel<<<BTOT / 256, 256>>>(z, zb);

    int total = NCHUNK * 16384 + KTOT;
    pack_kernel<<<(total + 255) / 256, 256>>>(W, R, U);

    cudaFuncSetAttribute(hmlstm_kernel,
                         cudaFuncAttributeMaxDynamicSharedMemorySize, SMEM_BYTES);
    hmlstm_kernel<<<2 * (BTOT / MT), THREADS, SMEM_BYTES>>>(hb, h, ht, c, z, zb, b, out);
}